// round 5
// baseline (speedup 1.0000x reference)
#include <cuda_runtime.h>
#include <cuda_bf16.h>
#include <cstdint>

#define NB 8
#define NC 64
#define NPTS 16384
#define NJ 128
#define NCH 64
#define FWD_CHUNK 256
#define FWD_TN 64
#define FWD_TILES 4
#define NCHI 64
#define INV_CHUNK 256
#define INV_TN 128
#define INV_TILES 2
#define TWO_PI_F 6.28318530717958647692f

#define FWD_AS 72   // row stride (elems) for fwd smem tiles (144 B)
#define INV_S 136   // row stride (elems) for inv smem tiles (272 B)

// fwd smem offsets (bytes)
#define F_AHI 0
#define F_ALO 18432
#define F_BHI 36864
#define F_BLO 46080
#define F_TOT 55296
// inv smem offsets
#define I_AHI 0          // MY hi   [64 o][136]
#define I_ALO 17408
#define I_BHI 34816      // basis hi [128 n][136]
#define I_BLO 69632
#define I_TOT 104448

__device__ float g_FTp[(size_t)NB * NCH * NJ * NC]; // 16 MB
__device__ float g_MY[(size_t)NB * NJ * NC];        // 256 KB

extern __shared__ __align__(16) char dsm[];

// ---------------------------------------------------------------------------
// helpers
// ---------------------------------------------------------------------------
__device__ __forceinline__ uint32_t smem_u32(const void* p) {
    uint32_t a;
    asm("{ .reg .u64 t; cvta.to.shared.u64 t, %1; cvt.u32.u64 %0, t; }" : "=r"(a) : "l"(p));
    return a;
}
__device__ __forceinline__ void ldsm4(uint32_t* r, uint32_t addr) {
    asm volatile("ldmatrix.sync.aligned.m8n8.x4.shared.b16 {%0,%1,%2,%3}, [%4];"
                 : "=r"(r[0]), "=r"(r[1]), "=r"(r[2]), "=r"(r[3]) : "r"(addr));
}
__device__ __forceinline__ void mma_bf16(float* d, const uint32_t* a, uint32_t b0, uint32_t b1) {
    asm volatile("mma.sync.aligned.m16n8k16.row.col.f32.bf16.bf16.f32 "
                 "{%0,%1,%2,%3}, {%4,%5,%6,%7}, {%8,%9}, {%0,%1,%2,%3};"
                 : "+f"(d[0]), "+f"(d[1]), "+f"(d[2]), "+f"(d[3])
                 : "r"(a[0]), "r"(a[1]), "r"(a[2]), "r"(a[3]), "r"(b0), "r"(b1));
}
__device__ __forceinline__ void split_bf16(float v, __nv_bfloat16& h, __nv_bfloat16& l) {
    h = __float2bfloat16_rn(v);
    l = __float2bfloat16_rn(v - __bfloat162float(h));
}
__device__ __forceinline__ uint32_t pk2(__nv_bfloat16 a, __nv_bfloat16 b) {
    return (uint32_t)__bfloat16_as_ushort(a) | ((uint32_t)__bfloat16_as_ushort(b) << 16);
}

// ---------------------------------------------------------------------------
// Forward: g_FTp[b][ch][j=128][c=64] = sum_n Bas[j][n] * x[c][n], n in 256-chunk
// A = basis [128 j][64 n] bf16 hi/lo, B = x [64 c][64 n]. 3-pass hi/lo HMMA.
// ---------------------------------------------------------------------------
__global__ __launch_bounds__(256, 3) void fwd_kernel(const float* __restrict__ x,
                                                     const float* __restrict__ x_in) {
    const int b = blockIdx.y, ch = blockIdx.x;
    const int tid = threadIdx.x, wid = tid >> 5, lane = tid & 31;

    __nv_bfloat16* AH = (__nv_bfloat16*)(dsm + F_AHI);
    __nv_bfloat16* AL = (__nv_bfloat16*)(dsm + F_ALO);
    __nv_bfloat16* BH = (__nv_bfloat16*)(dsm + F_BHI);
    __nv_bfloat16* BL = (__nv_bfloat16*)(dsm + F_BLO);

    const int j0 = (wid >> 2) * 64;
    const int c0 = (wid & 3) * 16;

    // ldmatrix lane addresses (bytes into smem)
    const uint32_t a_row = (uint32_t)(j0 + (lane & 7) + ((lane >> 3) & 1) * 8);
    const uint32_t a_col = (uint32_t)((lane >> 4) * 8);
    const uint32_t b_row = (uint32_t)(c0 + (lane & 7) + ((lane >> 3) & 1) * 8);
    const uint32_t base = smem_u32(dsm);
    const uint32_t AHIa = base + F_AHI + (a_row * FWD_AS + a_col) * 2;
    const uint32_t ALOa = base + F_ALO + (a_row * FWD_AS + a_col) * 2;
    const uint32_t BHIa = base + F_BHI + (b_row * FWD_AS + a_col) * 2;
    const uint32_t BLOa = base + F_BLO + (b_row * FWD_AS + a_col) * 2;

    // staging params
    const int cc = tid >> 2;
    const int nq = (tid & 3) * 16;
    const float* xr = x + ((size_t)b * NC + cc) * NPTS;

    // basis chain params: 1 chain per thread (n 0-63, br 0-1, khalf 0-1)
    const int cn  = tid & 63;
    const int cbr = (tid >> 6) & 1;
    const int ckh = tid >> 7;
    const int jc = cbr * 64 + ckh * 16; // cos rows
    const int js = jc + 32;             // sin rows

    float acc[4][2][4];
#pragma unroll
    for (int mi = 0; mi < 4; ++mi)
#pragma unroll
        for (int ni = 0; ni < 2; ++ni)
#pragma unroll
            for (int q = 0; q < 4; ++q) acc[mi][ni][q] = 0.f;

    for (int t = 0; t < FWD_TILES; ++t) {
        const int n0 = ch * FWD_CHUNK + t * FWD_TN;
        __syncthreads();
        // --- stage x tile ---
#pragma unroll
        for (int g = 0; g < 4; ++g) {
            float4 v = *reinterpret_cast<const float4*>(xr + n0 + nq + 4 * g);
            __nv_bfloat16 h0, l0, h1, l1, h2, l2, h3, l3;
            split_bf16(v.x, h0, l0); split_bf16(v.y, h1, l1);
            split_bf16(v.z, h2, l2); split_bf16(v.w, h3, l3);
            int col = nq + 4 * g;
            *reinterpret_cast<uint32_t*>(&BH[cc * FWD_AS + col])     = pk2(h0, h1);
            *reinterpret_cast<uint32_t*>(&BL[cc * FWD_AS + col])     = pk2(l0, l1);
            *reinterpret_cast<uint32_t*>(&BH[cc * FWD_AS + col + 2]) = pk2(h2, h3);
            *reinterpret_cast<uint32_t*>(&BL[cc * FWD_AS + col + 2]) = pk2(l2, l3);
        }
        // --- stage basis via recurrence chain ---
        {
            float p = x_in[((size_t)b * NPTS + n0 + cn) * 2 + cbr];
            float c1r, c1i;
            {
                float f = p - rintf(p);
                __sincosf(TWO_PI_F * f, &c1i, &c1r);
            }
            float cr, ci;
            if (ckh == 0) { cr = 1.f; ci = 0.f; }
            else {
                float f = 16.f * p;
                f -= rintf(f);
                __sincosf(TWO_PI_F * f, &ci, &cr);
            }
#pragma unroll
            for (int k = 0; k < 16; ++k) {
                __nv_bfloat16 hc, lc, hs, ls;
                split_bf16(cr, hc, lc);
                split_bf16(ci, hs, ls);
                AH[(jc + k) * FWD_AS + cn] = hc;
                AL[(jc + k) * FWD_AS + cn] = lc;
                AH[(js + k) * FWD_AS + cn] = hs;
                AL[(js + k) * FWD_AS + cn] = ls;
                float nr = fmaf(cr, c1r, -ci * c1i);
                float ni_ = fmaf(cr, c1i, ci * c1r);
                cr = nr; ci = ni_;
            }
        }
        __syncthreads();
        // --- MMA over 4 k-steps of 16 ---
#pragma unroll
        for (int ks = 0; ks < 4; ++ks) {
            const uint32_t co = (uint32_t)(ks * 16 * 2);
            uint32_t ah[4][4], al[4][4], bh[4], bl[4];
#pragma unroll
            for (int mi = 0; mi < 4; ++mi) {
                ldsm4(ah[mi], AHIa + mi * (16 * FWD_AS * 2) + co);
                ldsm4(al[mi], ALOa + mi * (16 * FWD_AS * 2) + co);
            }
            ldsm4(bh, BHIa + co);
            ldsm4(bl, BLOa + co);
#pragma unroll
            for (int mi = 0; mi < 4; ++mi)
#pragma unroll
                for (int ni = 0; ni < 2; ++ni) {
                    mma_bf16(acc[mi][ni], ah[mi], bh[ni], bh[ni + 2]);
                    mma_bf16(acc[mi][ni], ah[mi], bl[ni], bl[ni + 2]);
                    mma_bf16(acc[mi][ni], al[mi], bh[ni], bh[ni + 2]);
                }
        }
    }

    // epilogue: D[j][c] -> g_FTp
    float* outp = g_FTp + ((size_t)(b * NCH + ch)) * NJ * NC;
#pragma unroll
    for (int mi = 0; mi < 4; ++mi)
#pragma unroll
        for (int ni = 0; ni < 2; ++ni) {
            int jrow = j0 + 16 * mi + (lane >> 2);
            int ccol = c0 + 8 * ni + 2 * (lane & 3);
            float2 v0 = make_float2(acc[mi][ni][0], acc[mi][ni][1]);
            float2 v1 = make_float2(acc[mi][ni][2], acc[mi][ni][3]);
            *reinterpret_cast<float2*>(&outp[jrow * NC + ccol])       = v0;
            *reinterpret_cast<float2*>(&outp[(jrow + 8) * NC + ccol]) = v1;
        }
}

// ---------------------------------------------------------------------------
// Mix: reduce chunk partials, apply complex weights, fold signs, scale 64.
// ---------------------------------------------------------------------------
__global__ __launch_bounds__(64) void mix_kernel(const float* __restrict__ w1,
                                                 const float* __restrict__ w2) {
    const int k  = blockIdx.x;
    const int br = blockIdx.y;
    const int b  = blockIdx.z;
    const int o  = threadIdx.x;

    __shared__ float Ac[NC], As[NC];

    for (int v = threadIdx.x; v < 2 * NC; v += 64) {
        int cs = v >> 6;
        int i  = v & 63;
        int j  = br * 64 + cs * 32 + k;
        float s = 0.f;
        const float* basep = g_FTp + (size_t)b * NCH * NJ * NC + (size_t)j * NC + i;
        for (int c2 = 0; c2 < NCH; ++c2) s += basep[(size_t)c2 * NJ * NC];
        if (cs == 0) Ac[i] = s; else As[i] = s;
    }
    __syncthreads();

    const float* W = (br == 0) ? w1 : w2;
    float mr = 0.f, mi = 0.f;
    for (int i = 0; i < NC; ++i) {
        float2 w = *reinterpret_cast<const float2*>(W + (((size_t)i * 64 + o) * 32 + k) * 2);
        float ac = Ac[i], as = As[i];
        mr = fmaf(ac, w.x, mr);
        mr = fmaf(as, w.y, mr);
        mi = fmaf(ac, w.y, mi);
        mi = fmaf(-as, w.x, mi);
    }
    g_MY[((size_t)b * NJ + br * 64 + k) * NC + o]      = 64.f * mr;
    g_MY[((size_t)b * NJ + br * 64 + 32 + k) * NC + o] = -64.f * mi;
}

// ---------------------------------------------------------------------------
// Inverse: out[b][o][n] = sum_j MY[j][o] * Bas_out[j][n]
// HMMA with M = o (A = MY [64 o][128 j]), N = n (B = basis [128 n][128 j]).
// D frag cols = n -> direct coalesced float2 STG.
// ---------------------------------------------------------------------------
__global__ __launch_bounds__(256, 2) void inv_kernel(const float* __restrict__ x_out,
                                                     float* __restrict__ out) {
    const int b = blockIdx.y, ch = blockIdx.x;
    const int tid = threadIdx.x, wid = tid >> 5, lane = tid & 31;

    __nv_bfloat16* AH = (__nv_bfloat16*)(dsm + I_AHI);
    __nv_bfloat16* AL = (__nv_bfloat16*)(dsm + I_ALO);

    // stage MY once: [o rows][j cols], hi/lo
    for (int v = tid; v < NJ * NC; v += 256) {
        int o = v & 63;
        int j = v >> 6;
        float val = g_MY[((size_t)b * NJ + j) * NC + o];
        __nv_bfloat16 h, l;
        split_bf16(val, h, l);
        AH[o * INV_S + j] = h;
        AL[o * INV_S + j] = l;
    }

    const int o0 = (wid & 3) * 16;
    const int nh = (wid >> 2) * 64;

    const uint32_t base = smem_u32(dsm);
    const uint32_t a_row = (uint32_t)(o0 + (lane & 7) + ((lane >> 3) & 1) * 8);
    const uint32_t kcol = (uint32_t)((lane >> 4) * 8);
    const uint32_t AHIa = base + I_AHI + (a_row * INV_S + kcol) * 2;
    const uint32_t ALOa = base + I_ALO + (a_row * INV_S + kcol) * 2;
    const uint32_t b_row = (uint32_t)(nh + (lane & 7) + ((lane >> 3) & 1) * 8);
    const uint32_t BHIa = base + I_BHI + (b_row * INV_S + kcol) * 2;
    const uint32_t BLOa = base + I_BLO + (b_row * INV_S + kcol) * 2;

    for (int t = 0; t < INV_TILES; ++t) {
        const int n0 = ch * INV_CHUNK + t * INV_TN;
        __syncthreads();
        // --- stage basis [128 n][128 j] via chains, 2 chains/thread, vector STS ---
#pragma unroll
        for (int r = 0; r < 2; ++r) {
            int id  = tid + r * 256;
            int n   = id & 127;
            int cbr = (id >> 7) & 1;
            int ckh = id >> 8;
            float p = x_out[((size_t)b * NPTS + n0 + n) * 2 + cbr];
            float c1r, c1i;
            {
                float f = p - rintf(p);
                __sincosf(TWO_PI_F * f, &c1i, &c1r);
            }
            float cr, ci;
            if (ckh == 0) { cr = 1.f; ci = 0.f; }
            else {
                float f = 16.f * p;
                f -= rintf(f);
                __sincosf(TWO_PI_F * f, &ci, &cr);
            }
            uint32_t chb[8], clb[8], shb[8], slb[8];
#pragma unroll
            for (int kp = 0; kp < 8; ++kp) {
                __nv_bfloat16 hc0, lc0, hs0, ls0, hc1, lc1, hs1, ls1;
                split_bf16(cr, hc0, lc0);
                split_bf16(ci, hs0, ls0);
                {
                    float nr = fmaf(cr, c1r, -ci * c1i);
                    float ni_ = fmaf(cr, c1i, ci * c1r);
                    cr = nr; ci = ni_;
                }
                split_bf16(cr, hc1, lc1);
                split_bf16(ci, hs1, ls1);
                {
                    float nr = fmaf(cr, c1r, -ci * c1i);
                    float ni_ = fmaf(cr, c1i, ci * c1r);
                    cr = nr; ci = ni_;
                }
                chb[kp] = pk2(hc0, hc1);
                clb[kp] = pk2(lc0, lc1);
                shb[kp] = pk2(hs0, hs1);
                slb[kp] = pk2(ls0, ls1);
            }
            // row n, cos cols (cbr*64 + ckh*16 + k), sin +32  -> byte offsets
            uint32_t rowb = (uint32_t)(n * (INV_S * 2) + cbr * 128 + ckh * 32);
            char* BHp = dsm + I_BHI + rowb;
            char* BLp = dsm + I_BLO + rowb;
            *reinterpret_cast<uint4*>(BHp)          = *reinterpret_cast<uint4*>(&chb[0]);
            *reinterpret_cast<uint4*>(BHp + 16)     = *reinterpret_cast<uint4*>(&chb[4]);
            *reinterpret_cast<uint4*>(BLp)          = *reinterpret_cast<uint4*>(&clb[0]);
            *reinterpret_cast<uint4*>(BLp + 16)     = *reinterpret_cast<uint4*>(&clb[4]);
            *reinterpret_cast<uint4*>(BHp + 64)     = *reinterpret_cast<uint4*>(&shb[0]);
            *reinterpret_cast<uint4*>(BHp + 64 + 16)= *reinterpret_cast<uint4*>(&shb[4]);
            *reinterpret_cast<uint4*>(BLp + 64)     = *reinterpret_cast<uint4*>(&slb[0]);
            *reinterpret_cast<uint4*>(BLp + 64 + 16)= *reinterpret_cast<uint4*>(&slb[4]);
        }
        __syncthreads();

        // --- MMA: K = j = 128, 8 k-steps ---
        float acc[8][4];
#pragma unroll
        for (int ni = 0; ni < 8; ++ni)
#pragma unroll
            for (int q = 0; q < 4; ++q) acc[ni][q] = 0.f;

#pragma unroll
        for (int ks = 0; ks < 8; ++ks) {
            const uint32_t co = (uint32_t)(ks * 16 * 2);
            uint32_t ah[4], al[4], bh[4][4], bl[4][4];
            ldsm4(ah, AHIa + co);
            ldsm4(al, ALOa + co);
#pragma unroll
            for (int g = 0; g < 4; ++g) {
                ldsm4(bh[g], BHIa + g * (16 * INV_S * 2) + co);
                ldsm4(bl[g], BLOa + g * (16 * INV_S * 2) + co);
            }
#pragma unroll
            for (int ni = 0; ni < 8; ++ni) {
                int g = ni >> 1, h = ni & 1;
                mma_bf16(acc[ni], ah, bh[g][h], bh[g][h + 2]);
                mma_bf16(acc[ni], ah, bl[g][h], bl[g][h + 2]);
                mma_bf16(acc[ni], al, bh[g][h], bh[g][h + 2]);
            }
        }

        // --- epilogue: direct coalesced STG ---
        const int orow = o0 + (lane >> 2);
#pragma unroll
        for (int ni = 0; ni < 8; ++ni) {
            int n = n0 + nh + 8 * ni + 2 * (lane & 3);
            float2 v0 = make_float2(acc[ni][0], acc[ni][1]);
            float2 v1 = make_float2(acc[ni][2], acc[ni][3]);
            *reinterpret_cast<float2*>(&out[((size_t)(b * NC + orow)) * NPTS + n])     = v0;
            *reinterpret_cast<float2*>(&out[((size_t)(b * NC + orow + 8)) * NPTS + n]) = v1;
        }
    }
}

// ---------------------------------------------------------------------------
extern "C" void kernel_launch(void* const* d_in, const int* in_sizes, int n_in,
                              void* d_out, int out_size) {
    const float* x     = (const float*)d_in[0];
    const float* x_in  = (const float*)d_in[1];
    const float* x_out = (const float*)d_in[2];
    const float* w1    = (const float*)d_in[3];
    const float* w2    = (const float*)d_in[4];
    float* out = (float*)d_out;

    cudaFuncSetAttribute(fwd_kernel, cudaFuncAttributeMaxDynamicSharedMemorySize, F_TOT);
    cudaFuncSetAttribute(inv_kernel, cudaFuncAttributeMaxDynamicSharedMemorySize, I_TOT);

    fwd_kernel<<<dim3(NCH, NB), 256, F_TOT>>>(x, x_in);
    mix_kernel<<<dim3(32, 2, NB), 64>>>(w1, w2);
    inv_kernel<<<dim3(NCHI, NB), 256, I_TOT>>>(x_out, out);
}

// round 6
// speedup vs baseline: 1.2840x; 1.2840x over previous
#include <cuda_runtime.h>
#include <cuda_fp16.h>
#include <cstdint>

#define NB 8
#define NC 64
#define NPTS 16384
#define NJ 128
#define NCH 32
#define FWD_CHUNK 512
#define FWD_TN 64
#define FWD_TILES 8
#define NCHI 32
#define INV_CHUNK 512
#define INV_TN 128
#define INV_TILES 4
#define TWO_PI_F 6.28318530717958647692f

#define FWD_AS 72   // fwd row stride (elems), 144 B
#define INV_S 136   // inv row stride (elems), 272 B

// fwd smem per buffer: A basis [128][72] f16 =18432 ; BH x hi [64][72]=9216 ; BL=9216
#define F_A   0
#define F_BH  18432
#define F_BL  27648
#define F_BUF 36864
#define F_TOT (2 * F_BUF)       // 73728
// inv smem: MY hi/lo static + basis double buffer
#define I_AH  0
#define I_AL  17408
#define I_B   34816
#define I_BUF 34816
#define I_TOT (I_B + 2 * I_BUF) // 104448

__device__ float g_FTp[(size_t)NB * NCH * NJ * NC]; // 8 MB
__device__ float g_MY[(size_t)NB * NJ * NC];        // 256 KB

extern __shared__ __align__(16) char dsm[];

// ---------------------------------------------------------------------------
// helpers
// ---------------------------------------------------------------------------
__device__ __forceinline__ uint32_t smem_u32(const void* p) {
    uint32_t a;
    asm("{ .reg .u64 t; cvta.to.shared.u64 t, %1; cvt.u32.u64 %0, t; }" : "=r"(a) : "l"(p));
    return a;
}
__device__ __forceinline__ void ldsm4(uint32_t* r, uint32_t addr) {
    asm volatile("ldmatrix.sync.aligned.m8n8.x4.shared.b16 {%0,%1,%2,%3}, [%4];"
                 : "=r"(r[0]), "=r"(r[1]), "=r"(r[2]), "=r"(r[3]) : "r"(addr));
}
__device__ __forceinline__ void mma_f16(float* d, const uint32_t* a, uint32_t b0, uint32_t b1) {
    asm volatile("mma.sync.aligned.m16n8k16.row.col.f32.f16.f16.f32 "
                 "{%0,%1,%2,%3}, {%4,%5,%6,%7}, {%8,%9}, {%0,%1,%2,%3};"
                 : "+f"(d[0]), "+f"(d[1]), "+f"(d[2]), "+f"(d[3])
                 : "r"(a[0]), "r"(a[1]), "r"(a[2]), "r"(a[3]), "r"(b0), "r"(b1));
}
__device__ __forceinline__ void split_f16(float v, __half& h, __half& l) {
    h = __float2half_rn(v);
    l = __float2half_rn(v - __half2float(h));
}
__device__ __forceinline__ uint32_t pk2h(__half a, __half b) {
    return (uint32_t)__half_as_ushort(a) | ((uint32_t)__half_as_ushort(b) << 16);
}

// ---------------------------------------------------------------------------
// Forward: g_FTp[b][ch][j=128][c=64] = sum_n Bas[j][n] * x[c][n] (512-chunk)
// A = basis single f16, B = x hi/lo f16. 2-pass HMMA, double-buffered.
// ---------------------------------------------------------------------------
__global__ __launch_bounds__(256, 3) void fwd_kernel(const float* __restrict__ x,
                                                     const float* __restrict__ x_in) {
    const int b = blockIdx.y, ch = blockIdx.x;
    const int tid = threadIdx.x, wid = tid >> 5, lane = tid & 31;

    const int j0 = (wid >> 2) * 64;
    const int c0 = (wid & 3) * 16;

    const uint32_t base = smem_u32(dsm);
    const uint32_t a_row = (uint32_t)(j0 + (lane & 7) + ((lane >> 3) & 1) * 8);
    const uint32_t a_col = (uint32_t)((lane >> 4) * 8);
    const uint32_t b_row = (uint32_t)(c0 + (lane & 7) + ((lane >> 3) & 1) * 8);
    const uint32_t Aa  = base + F_A  + (a_row * FWD_AS + a_col) * 2;
    const uint32_t BHa = base + F_BH + (b_row * FWD_AS + a_col) * 2;
    const uint32_t BLa = base + F_BL + (b_row * FWD_AS + a_col) * 2;

    // staging params
    const int cc = tid >> 2;
    const int nq = (tid & 3) * 16;
    const float* xr = x + ((size_t)b * NC + cc) * NPTS;

    // basis chain: 1 chain/thread (n 0-63, br 0-1, khalf 0-1)
    const int cn  = tid & 63;
    const int cbr = (tid >> 6) & 1;
    const int ckh = tid >> 7;
    const int jc = cbr * 64 + ckh * 16;
    const int js = jc + 32;

    float acc[4][2][4];
#pragma unroll
    for (int mi = 0; mi < 4; ++mi)
#pragma unroll
        for (int ni = 0; ni < 2; ++ni)
#pragma unroll
            for (int q = 0; q < 4; ++q) acc[mi][ni][q] = 0.f;

    for (int t = 0; t < FWD_TILES; ++t) {
        const int n0 = ch * FWD_CHUNK + t * FWD_TN;
        const uint32_t woff = (uint32_t)(t & 1) * F_BUF;
        __half* AS = (__half*)(dsm + woff + F_A);
        __half* BH = (__half*)(dsm + woff + F_BH);
        __half* BL = (__half*)(dsm + woff + F_BL);

        __syncthreads();

        // ---- issue long-latency loads for tile t ----
        float4 xv[4];
#pragma unroll
        for (int g = 0; g < 4; ++g)
            xv[g] = *reinterpret_cast<const float4*>(xr + n0 + nq + 4 * g);
        float p = x_in[((size_t)b * NPTS + n0 + cn) * 2 + cbr];
        float c1r, c1i, cr, ci;
        {
            float f = p - rintf(p);
            __sincosf(TWO_PI_F * f, &c1i, &c1r);
        }
        if (ckh == 0) { cr = 1.f; ci = 0.f; }
        else {
            float f = 16.f * p;
            f -= rintf(f);
            __sincosf(TWO_PI_F * f, &ci, &cr);
        }

        // ---- MMA tile t-1 (other buffer) overlapped with staging ----
        if (t > 0) {
            const uint32_t roff = (uint32_t)((t - 1) & 1) * F_BUF;
#pragma unroll
            for (int ks = 0; ks < 4; ++ks) {
                const uint32_t co = roff + (uint32_t)(ks * 16 * 2);
                uint32_t ah[4][4], bh[4], bl[4];
#pragma unroll
                for (int mi = 0; mi < 4; ++mi)
                    ldsm4(ah[mi], Aa + mi * (16 * FWD_AS * 2) + co);
                ldsm4(bh, BHa + co);
                ldsm4(bl, BLa + co);
#pragma unroll
                for (int mi = 0; mi < 4; ++mi)
#pragma unroll
                    for (int ni = 0; ni < 2; ++ni) {
                        mma_f16(acc[mi][ni], ah[mi], bh[ni], bh[ni + 2]);
                        mma_f16(acc[mi][ni], ah[mi], bl[ni], bl[ni + 2]);
                    }
            }
        }

        // ---- store x tile hi/lo ----
#pragma unroll
        for (int g = 0; g < 4; ++g) {
            __half h0, l0, h1, l1, h2, l2, h3, l3;
            split_f16(xv[g].x, h0, l0); split_f16(xv[g].y, h1, l1);
            split_f16(xv[g].z, h2, l2); split_f16(xv[g].w, h3, l3);
            int col = nq + 4 * g;
            *reinterpret_cast<uint32_t*>(&BH[cc * FWD_AS + col])     = pk2h(h0, h1);
            *reinterpret_cast<uint32_t*>(&BL[cc * FWD_AS + col])     = pk2h(l0, l1);
            *reinterpret_cast<uint32_t*>(&BH[cc * FWD_AS + col + 2]) = pk2h(h2, h3);
            *reinterpret_cast<uint32_t*>(&BL[cc * FWD_AS + col + 2]) = pk2h(l2, l3);
        }
        // ---- basis chain (single f16) ----
#pragma unroll
        for (int k = 0; k < 16; ++k) {
            AS[(jc + k) * FWD_AS + cn] = __float2half_rn(cr);
            AS[(js + k) * FWD_AS + cn] = __float2half_rn(ci);
            float nr = fmaf(cr, c1r, -ci * c1i);
            float ni_ = fmaf(cr, c1i, ci * c1r);
            cr = nr; ci = ni_;
        }
    }
    // drain last tile
    __syncthreads();
    {
        const uint32_t roff = (uint32_t)((FWD_TILES - 1) & 1) * F_BUF;
#pragma unroll
        for (int ks = 0; ks < 4; ++ks) {
            const uint32_t co = roff + (uint32_t)(ks * 16 * 2);
            uint32_t ah[4][4], bh[4], bl[4];
#pragma unroll
            for (int mi = 0; mi < 4; ++mi)
                ldsm4(ah[mi], Aa + mi * (16 * FWD_AS * 2) + co);
            ldsm4(bh, BHa + co);
            ldsm4(bl, BLa + co);
#pragma unroll
            for (int mi = 0; mi < 4; ++mi)
#pragma unroll
                for (int ni = 0; ni < 2; ++ni) {
                    mma_f16(acc[mi][ni], ah[mi], bh[ni], bh[ni + 2]);
                    mma_f16(acc[mi][ni], ah[mi], bl[ni], bl[ni + 2]);
                }
        }
    }

    // epilogue: D[j][c] -> g_FTp
    float* outp = g_FTp + ((size_t)(b * NCH + ch)) * NJ * NC;
#pragma unroll
    for (int mi = 0; mi < 4; ++mi)
#pragma unroll
        for (int ni = 0; ni < 2; ++ni) {
            int jrow = j0 + 16 * mi + (lane >> 2);
            int ccol = c0 + 8 * ni + 2 * (lane & 3);
            float2 v0 = make_float2(acc[mi][ni][0], acc[mi][ni][1]);
            float2 v1 = make_float2(acc[mi][ni][2], acc[mi][ni][3]);
            *reinterpret_cast<float2*>(&outp[jrow * NC + ccol])       = v0;
            *reinterpret_cast<float2*>(&outp[(jrow + 8) * NC + ccol]) = v1;
        }
}

// ---------------------------------------------------------------------------
// Mix: reduce chunk partials, apply complex weights (no x64 fold here).
//  g_MY[b][br*64+k][o] = mr ; g_MY[b][br*64+32+k][o] = -mi
// ---------------------------------------------------------------------------
__global__ __launch_bounds__(64) void mix_kernel(const float* __restrict__ w1,
                                                 const float* __restrict__ w2) {
    const int k  = blockIdx.x;
    const int br = blockIdx.y;
    const int b  = blockIdx.z;
    const int o  = threadIdx.x;

    __shared__ float Ac[NC], As[NC];

    for (int v = threadIdx.x; v < 2 * NC; v += 64) {
        int cs = v >> 6;
        int i  = v & 63;
        int j  = br * 64 + cs * 32 + k;
        float s = 0.f;
        const float* basep = g_FTp + (size_t)b * NCH * NJ * NC + (size_t)j * NC + i;
        for (int c2 = 0; c2 < NCH; ++c2) s += basep[(size_t)c2 * NJ * NC];
        if (cs == 0) Ac[i] = s; else As[i] = s;
    }
    __syncthreads();

    const float* W = (br == 0) ? w1 : w2;
    float mr = 0.f, mi = 0.f;
    for (int i = 0; i < NC; ++i) {
        float2 w = *reinterpret_cast<const float2*>(W + (((size_t)i * 64 + o) * 32 + k) * 2);
        float ac = Ac[i], as = As[i];
        mr = fmaf(ac, w.x, mr);
        mr = fmaf(as, w.y, mr);
        mi = fmaf(ac, w.y, mi);
        mi = fmaf(-as, w.x, mi);
    }
    g_MY[((size_t)b * NJ + br * 64 + k) * NC + o]      = mr;
    g_MY[((size_t)b * NJ + br * 64 + 32 + k) * NC + o] = -mi;
}

// ---------------------------------------------------------------------------
// Inverse: out[b][o][n] = 64 * sum_j MY[j][o] * Bas_out[j][n]
// A = MY hi/lo f16 (static), B = basis single f16 (double-buffered).
// ---------------------------------------------------------------------------
__global__ __launch_bounds__(256, 2) void inv_kernel(const float* __restrict__ x_out,
                                                     float* __restrict__ out) {
    const int b = blockIdx.y, ch = blockIdx.x;
    const int tid = threadIdx.x, wid = tid >> 5, lane = tid & 31;

    __half* AH = (__half*)(dsm + I_AH);
    __half* AL = (__half*)(dsm + I_AL);

    // stage MY once: [o rows][j cols], hi/lo
    for (int v = tid; v < NJ * NC; v += 256) {
        int o = v & 63;
        int j = v >> 6;
        float val = g_MY[((size_t)b * NJ + j) * NC + o];
        __half h, l;
        split_f16(val, h, l);
        AH[o * INV_S + j] = h;
        AL[o * INV_S + j] = l;
    }

    const int o0 = (wid & 3) * 16;
    const int nh = (wid >> 2) * 64;

    const uint32_t base = smem_u32(dsm);
    const uint32_t a_row = (uint32_t)(o0 + (lane & 7) + ((lane >> 3) & 1) * 8);
    const uint32_t kcol = (uint32_t)((lane >> 4) * 8);
    const uint32_t AHa = base + I_AH + (a_row * INV_S + kcol) * 2;
    const uint32_t ALa = base + I_AL + (a_row * INV_S + kcol) * 2;
    const uint32_t b_row = (uint32_t)(nh + (lane & 7) + ((lane >> 3) & 1) * 8);
    const uint32_t Ba = base + I_B + (b_row * INV_S + kcol) * 2;

    float acc[8][4];
    const int orow = o0 + (lane >> 2);

    for (int t = 0; t < INV_TILES + 1; ++t) {
        __syncthreads();
        // ---- stage basis tile t into buf t&1 ----
        if (t < INV_TILES) {
            const int n0 = ch * INV_CHUNK + t * INV_TN;
            char* Bbuf = dsm + I_B + (uint32_t)(t & 1) * I_BUF;
#pragma unroll
            for (int r = 0; r < 2; ++r) {
                int id  = tid + r * 256;
                int n   = id & 127;
                int cbr = (id >> 7) & 1;
                int ckh = id >> 8;
                float p = x_out[((size_t)b * NPTS + n0 + n) * 2 + cbr];
                float c1r, c1i, cr, ci;
                {
                    float f = p - rintf(p);
                    __sincosf(TWO_PI_F * f, &c1i, &c1r);
                }
                if (ckh == 0) { cr = 1.f; ci = 0.f; }
                else {
                    float f = 16.f * p;
                    f -= rintf(f);
                    __sincosf(TWO_PI_F * f, &ci, &cr);
                }
                uint32_t chb[8], shb[8];
#pragma unroll
                for (int kp = 0; kp < 8; ++kp) {
                    __half hc0 = __float2half_rn(cr);
                    __half hs0 = __float2half_rn(ci);
                    {
                        float nr = fmaf(cr, c1r, -ci * c1i);
                        float ni_ = fmaf(cr, c1i, ci * c1r);
                        cr = nr; ci = ni_;
                    }
                    __half hc1 = __float2half_rn(cr);
                    __half hs1 = __float2half_rn(ci);
                    {
                        float nr = fmaf(cr, c1r, -ci * c1i);
                        float ni_ = fmaf(cr, c1i, ci * c1r);
                        cr = nr; ci = ni_;
                    }
                    chb[kp] = pk2h(hc0, hc1);
                    shb[kp] = pk2h(hs0, hs1);
                }
                uint32_t rowb = (uint32_t)(n * (INV_S * 2) + cbr * 128 + ckh * 32);
                char* Bp = Bbuf + rowb;
                *reinterpret_cast<uint4*>(Bp)           = *reinterpret_cast<uint4*>(&chb[0]);
                *reinterpret_cast<uint4*>(Bp + 16)      = *reinterpret_cast<uint4*>(&chb[4]);
                *reinterpret_cast<uint4*>(Bp + 64)      = *reinterpret_cast<uint4*>(&shb[0]);
                *reinterpret_cast<uint4*>(Bp + 64 + 16) = *reinterpret_cast<uint4*>(&shb[4]);
            }
        }
        // ---- MMA tile t-1 from buf (t-1)&1, then store ----
        if (t > 0) {
            const int n0 = ch * INV_CHUNK + (t - 1) * INV_TN;
            const uint32_t roff = (uint32_t)((t - 1) & 1) * I_BUF;
#pragma unroll
            for (int ni = 0; ni < 8; ++ni)
#pragma unroll
                for (int q = 0; q < 4; ++q) acc[ni][q] = 0.f;
#pragma unroll
            for (int ks = 0; ks < 8; ++ks) {
                const uint32_t co = (uint32_t)(ks * 16 * 2);
                uint32_t ah[4], al[4], bh[4][4];
                ldsm4(ah, AHa + co);
                ldsm4(al, ALa + co);
#pragma unroll
                for (int g = 0; g < 4; ++g)
                    ldsm4(bh[g], Ba + roff + g * (16 * INV_S * 2) + co);
#pragma unroll
                for (int ni = 0; ni < 8; ++ni) {
                    int g = ni >> 1, h = ni & 1;
                    mma_f16(acc[ni], ah, bh[g][h], bh[g][h + 2]);
                    mma_f16(acc[ni], al, bh[g][h], bh[g][h + 2]);
                }
            }
#pragma unroll
            for (int ni = 0; ni < 8; ++ni) {
                int n = n0 + nh + 8 * ni + 2 * (lane & 3);
                float2 v0 = make_float2(64.f * acc[ni][0], 64.f * acc[ni][1]);
                float2 v1 = make_float2(64.f * acc[ni][2], 64.f * acc[ni][3]);
                *reinterpret_cast<float2*>(&out[((size_t)(b * NC + orow)) * NPTS + n])     = v0;
                *reinterpret_cast<float2*>(&out[((size_t)(b * NC + orow + 8)) * NPTS + n]) = v1;
            }
        }
    }
}

// ---------------------------------------------------------------------------
extern "C" void kernel_launch(void* const* d_in, const int* in_sizes, int n_in,
                              void* d_out, int out_size) {
    const float* x     = (const float*)d_in[0];
    const float* x_in  = (const float*)d_in[1];
    const float* x_out = (const float*)d_in[2];
    const float* w1    = (const float*)d_in[3];
    const float* w2    = (const float*)d_in[4];
    float* out = (float*)d_out;

    cudaFuncSetAttribute(fwd_kernel, cudaFuncAttributeMaxDynamicSharedMemorySize, F_TOT);
    cudaFuncSetAttribute(inv_kernel, cudaFuncAttributeMaxDynamicSharedMemorySize, I_TOT);

    fwd_kernel<<<dim3(NCH, NB), 256, F_TOT>>>(x, x_in);
    mix_kernel<<<dim3(32, 2, NB), 64>>>(w1, w2);
    inv_kernel<<<dim3(NCHI, NB), 256, I_TOT>>>(x_out, out);
}

// round 7
// speedup vs baseline: 1.3681x; 1.0655x over previous
#include <cuda_runtime.h>
#include <cuda_fp16.h>
#include <cstdint>

#define NB 8
#define NC 64
#define NPTS 16384
#define NJ 128
#define NCH 32
#define FWD_CHUNK 512
#define FWD_TN 128
#define FWD_TILES 4
#define NCHI 32
#define INV_CHUNK 512
#define INV_TN 128
#define INV_TILES 4
#define TWO_PI_F 6.28318530717958647692f

#define FWD_S 136   // fwd row stride (elems), 272 B
#define INV_S 136   // inv row stride (elems), 272 B

// fwd smem per buffer: A basis [128 j][136] f16 = 34816 ; B x [64 c][136] f16 = 17408
#define F_A   0
#define F_B   34816
#define F_BUF 52224
#define F_TOT (2 * F_BUF)       // 104448
// inv smem: MY f16 static + basis double buffer
#define I_A   0
#define I_B   17408
#define I_BUF 34816
#define I_TOT (I_B + 2 * I_BUF) // 87040

__device__ float g_FTp[(size_t)NB * NCH * NJ * NC]; // 8 MB
__device__ float g_MY[(size_t)NB * NJ * NC];        // 256 KB

extern __shared__ __align__(16) char dsm[];

// ---------------------------------------------------------------------------
// helpers
// ---------------------------------------------------------------------------
__device__ __forceinline__ uint32_t smem_u32(const void* p) {
    uint32_t a;
    asm("{ .reg .u64 t; cvta.to.shared.u64 t, %1; cvt.u32.u64 %0, t; }" : "=r"(a) : "l"(p));
    return a;
}
__device__ __forceinline__ void ldsm4(uint32_t* r, uint32_t addr) {
    asm volatile("ldmatrix.sync.aligned.m8n8.x4.shared.b16 {%0,%1,%2,%3}, [%4];"
                 : "=r"(r[0]), "=r"(r[1]), "=r"(r[2]), "=r"(r[3]) : "r"(addr));
}
__device__ __forceinline__ void mma_f16(float* d, const uint32_t* a, uint32_t b0, uint32_t b1) {
    asm volatile("mma.sync.aligned.m16n8k16.row.col.f32.f16.f16.f32 "
                 "{%0,%1,%2,%3}, {%4,%5,%6,%7}, {%8,%9}, {%0,%1,%2,%3};"
                 : "+f"(d[0]), "+f"(d[1]), "+f"(d[2]), "+f"(d[3])
                 : "r"(a[0]), "r"(a[1]), "r"(a[2]), "r"(a[3]), "r"(b0), "r"(b1));
}
__device__ __forceinline__ uint32_t pk2h(__half a, __half b) {
    return (uint32_t)__half_as_ushort(a) | ((uint32_t)__half_as_ushort(b) << 16);
}

// ---------------------------------------------------------------------------
// Forward: g_FTp[b][ch][j=128][c=64] = sum_n Bas[j][n] * x[c][n] (512-chunk)
// Single-pass f16 both operands. Tiles of 128 n, double-buffered.
// ---------------------------------------------------------------------------
__global__ __launch_bounds__(256, 2) void fwd_kernel(const float* __restrict__ x,
                                                     const float* __restrict__ x_in) {
    const int b = blockIdx.y, ch = blockIdx.x;
    const int tid = threadIdx.x, wid = tid >> 5, lane = tid & 31;

    const int j0 = (wid >> 2) * 64;
    const int c0 = (wid & 3) * 16;

    const uint32_t base = smem_u32(dsm);
    const uint32_t a_row = (uint32_t)(j0 + (lane & 7) + ((lane >> 3) & 1) * 8);
    const uint32_t a_col = (uint32_t)((lane >> 4) * 8);
    const uint32_t b_row = (uint32_t)(c0 + (lane & 7) + ((lane >> 3) & 1) * 8);
    const uint32_t Aa = base + F_A + (a_row * FWD_S + a_col) * 2;
    const uint32_t Ba = base + F_B + (b_row * FWD_S + a_col) * 2;

    // staging params: x tile [64 c][128 n]; thread handles 32 n of one c row
    const int cc = tid >> 2;
    const int nq = (tid & 3) * 32;
    const float* xr = x + ((size_t)b * NC + cc) * NPTS;

    // basis chain: thread = (n 0..127, br 0..1); chain over all 32 k
    const int cn  = tid & 127;
    const int cbr = tid >> 7;
    const int jc = cbr * 64;       // cos rows
    const int js = jc + 32;        // sin rows

    float acc[4][2][4];
#pragma unroll
    for (int mi = 0; mi < 4; ++mi)
#pragma unroll
        for (int ni = 0; ni < 2; ++ni)
#pragma unroll
            for (int q = 0; q < 4; ++q) acc[mi][ni][q] = 0.f;

    for (int t = 0; t < FWD_TILES; ++t) {
        const int n0 = ch * FWD_CHUNK + t * FWD_TN;
        const uint32_t woff = (uint32_t)(t & 1) * F_BUF;
        __half* AS = (__half*)(dsm + woff + F_A);
        __half* BS = (__half*)(dsm + woff + F_B);

        __syncthreads();

        // ---- issue long-latency loads for tile t ----
        float4 xv[8];
#pragma unroll
        for (int g = 0; g < 8; ++g)
            xv[g] = *reinterpret_cast<const float4*>(xr + n0 + nq + 4 * g);
        float p = x_in[((size_t)b * NPTS + n0 + cn) * 2 + cbr];
        float c1r, c1i;
        {
            float f = p - rintf(p);
            __sincosf(TWO_PI_F * f, &c1i, &c1r);
        }

        // ---- MMA tile t-1 (other buffer) overlapped with staging ----
        if (t > 0) {
            const uint32_t roff = (uint32_t)((t - 1) & 1) * F_BUF;
#pragma unroll
            for (int ks = 0; ks < 8; ++ks) {
                const uint32_t co = roff + (uint32_t)(ks * 16 * 2);
                uint32_t ah[4][4], bh[4];
#pragma unroll
                for (int mi = 0; mi < 4; ++mi)
                    ldsm4(ah[mi], Aa + mi * (16 * FWD_S * 2) + co);
                ldsm4(bh, Ba + co);
#pragma unroll
                for (int mi = 0; mi < 4; ++mi)
#pragma unroll
                    for (int ni = 0; ni < 2; ++ni)
                        mma_f16(acc[mi][ni], ah[mi], bh[ni], bh[ni + 2]);
            }
        }

        // ---- store x tile f16 ----
#pragma unroll
        for (int g = 0; g < 8; ++g) {
            int col = nq + 4 * g;
            *reinterpret_cast<uint32_t*>(&BS[cc * FWD_S + col]) =
                pk2h(__float2half_rn(xv[g].x), __float2half_rn(xv[g].y));
            *reinterpret_cast<uint32_t*>(&BS[cc * FWD_S + col + 2]) =
                pk2h(__float2half_rn(xv[g].z), __float2half_rn(xv[g].w));
        }
        // ---- basis chain: k = 0..31 ----
        {
            float cr = 1.f, ci = 0.f;
#pragma unroll
            for (int k = 0; k < 32; ++k) {
                AS[(jc + k) * FWD_S + cn] = __float2half_rn(cr);
                AS[(js + k) * FWD_S + cn] = __float2half_rn(ci);
                float nr = fmaf(cr, c1r, -ci * c1i);
                float ni_ = fmaf(cr, c1i, ci * c1r);
                cr = nr; ci = ni_;
            }
        }
    }
    // drain last tile
    __syncthreads();
    {
        const uint32_t roff = (uint32_t)((FWD_TILES - 1) & 1) * F_BUF;
#pragma unroll
        for (int ks = 0; ks < 8; ++ks) {
            const uint32_t co = roff + (uint32_t)(ks * 16 * 2);
            uint32_t ah[4][4], bh[4];
#pragma unroll
            for (int mi = 0; mi < 4; ++mi)
                ldsm4(ah[mi], Aa + mi * (16 * FWD_S * 2) + co);
            ldsm4(bh, Ba + co);
#pragma unroll
            for (int mi = 0; mi < 4; ++mi)
#pragma unroll
                for (int ni = 0; ni < 2; ++ni)
                    mma_f16(acc[mi][ni], ah[mi], bh[ni], bh[ni + 2]);
        }
    }

    // epilogue: D[j][c] -> g_FTp
    float* outp = g_FTp + ((size_t)(b * NCH + ch)) * NJ * NC;
#pragma unroll
    for (int mi = 0; mi < 4; ++mi)
#pragma unroll
        for (int ni = 0; ni < 2; ++ni) {
            int jrow = j0 + 16 * mi + (lane >> 2);
            int ccol = c0 + 8 * ni + 2 * (lane & 3);
            float2 v0 = make_float2(acc[mi][ni][0], acc[mi][ni][1]);
            float2 v1 = make_float2(acc[mi][ni][2], acc[mi][ni][3]);
            *reinterpret_cast<float2*>(&outp[jrow * NC + ccol])       = v0;
            *reinterpret_cast<float2*>(&outp[(jrow + 8) * NC + ccol]) = v1;
        }
}

// ---------------------------------------------------------------------------
// Mix: reduce chunk partials, apply complex weights (no x64 fold here).
//  g_MY[b][br*64+k][o] = mr ; g_MY[b][br*64+32+k][o] = -mi
// ---------------------------------------------------------------------------
__global__ __launch_bounds__(64) void mix_kernel(const float* __restrict__ w1,
                                                 const float* __restrict__ w2) {
    const int k  = blockIdx.x;
    const int br = blockIdx.y;
    const int b  = blockIdx.z;
    const int o  = threadIdx.x;

    __shared__ float Ac[NC], As[NC];

    for (int v = threadIdx.x; v < 2 * NC; v += 64) {
        int cs = v >> 6;
        int i  = v & 63;
        int j  = br * 64 + cs * 32 + k;
        float s = 0.f;
        const float* basep = g_FTp + (size_t)b * NCH * NJ * NC + (size_t)j * NC + i;
        for (int c2 = 0; c2 < NCH; ++c2) s += basep[(size_t)c2 * NJ * NC];
        if (cs == 0) Ac[i] = s; else As[i] = s;
    }
    __syncthreads();

    const float* W = (br == 0) ? w1 : w2;
    float mr = 0.f, mi = 0.f;
    for (int i = 0; i < NC; ++i) {
        float2 w = *reinterpret_cast<const float2*>(W + (((size_t)i * 64 + o) * 32 + k) * 2);
        float ac = Ac[i], as = As[i];
        mr = fmaf(ac, w.x, mr);
        mr = fmaf(as, w.y, mr);
        mi = fmaf(ac, w.y, mi);
        mi = fmaf(-as, w.x, mi);
    }
    g_MY[((size_t)b * NJ + br * 64 + k) * NC + o]      = mr;
    g_MY[((size_t)b * NJ + br * 64 + 32 + k) * NC + o] = -mi;
}

// ---------------------------------------------------------------------------
// Inverse: out[b][o][n] = 64 * sum_j MY[j][o] * Bas_out[j][n]
// A = MY single f16 (static), B = basis single f16 (double-buffered).
// ---------------------------------------------------------------------------
__global__ __launch_bounds__(256, 2) void inv_kernel(const float* __restrict__ x_out,
                                                     float* __restrict__ out) {
    const int b = blockIdx.y, ch = blockIdx.x;
    const int tid = threadIdx.x, wid = tid >> 5, lane = tid & 31;

    __half* AS = (__half*)(dsm + I_A);

    // stage MY once: [o rows][j cols], single f16
    for (int v = tid; v < NJ * NC; v += 256) {
        int o = v & 63;
        int j = v >> 6;
        AS[o * INV_S + j] = __float2half_rn(g_MY[((size_t)b * NJ + j) * NC + o]);
    }

    const int o0 = (wid & 3) * 16;
    const int nh = (wid >> 2) * 64;

    const uint32_t base = smem_u32(dsm);
    const uint32_t a_row = (uint32_t)(o0 + (lane & 7) + ((lane >> 3) & 1) * 8);
    const uint32_t kcol = (uint32_t)((lane >> 4) * 8);
    const uint32_t Aa = base + I_A + (a_row * INV_S + kcol) * 2;
    const uint32_t b_row = (uint32_t)(nh + (lane & 7) + ((lane >> 3) & 1) * 8);
    const uint32_t Ba = base + I_B + (b_row * INV_S + kcol) * 2;

    float acc[8][4];
    const int orow = o0 + (lane >> 2);

    for (int t = 0; t < INV_TILES + 1; ++t) {
        __syncthreads();
        // ---- stage basis tile t into buf t&1 ----
        if (t < INV_TILES) {
            const int n0 = ch * INV_CHUNK + t * INV_TN;
            char* Bbuf = dsm + I_B + (uint32_t)(t & 1) * I_BUF;
#pragma unroll
            for (int r = 0; r < 2; ++r) {
                int id  = tid + r * 256;
                int n   = id & 127;
                int cbr = (id >> 7) & 1;
                int ckh = id >> 8;
                float p = x_out[((size_t)b * NPTS + n0 + n) * 2 + cbr];
                float c1r, c1i, cr, ci;
                {
                    float f = p - rintf(p);
                    __sincosf(TWO_PI_F * f, &c1i, &c1r);
                }
                if (ckh == 0) { cr = 1.f; ci = 0.f; }
                else {
                    float f = 16.f * p;
                    f -= rintf(f);
                    __sincosf(TWO_PI_F * f, &ci, &cr);
                }
                uint32_t chb[8], shb[8];
#pragma unroll
                for (int kp = 0; kp < 8; ++kp) {
                    __half hc0 = __float2half_rn(cr);
                    __half hs0 = __float2half_rn(ci);
                    {
                        float nr = fmaf(cr, c1r, -ci * c1i);
                        float ni_ = fmaf(cr, c1i, ci * c1r);
                        cr = nr; ci = ni_;
                    }
                    __half hc1 = __float2half_rn(cr);
                    __half hs1 = __float2half_rn(ci);
                    {
                        float nr = fmaf(cr, c1r, -ci * c1i);
                        float ni_ = fmaf(cr, c1i, ci * c1r);
                        cr = nr; ci = ni_;
                    }
                    chb[kp] = pk2h(hc0, hc1);
                    shb[kp] = pk2h(hs0, hs1);
                }
                uint32_t rowb = (uint32_t)(n * (INV_S * 2) + cbr * 128 + ckh * 32);
                char* Bp = Bbuf + rowb;
                *reinterpret_cast<uint4*>(Bp)           = *reinterpret_cast<uint4*>(&chb[0]);
                *reinterpret_cast<uint4*>(Bp + 16)      = *reinterpret_cast<uint4*>(&chb[4]);
                *reinterpret_cast<uint4*>(Bp + 64)      = *reinterpret_cast<uint4*>(&shb[0]);
                *reinterpret_cast<uint4*>(Bp + 64 + 16) = *reinterpret_cast<uint4*>(&shb[4]);
            }
        }
        // ---- MMA tile t-1 from buf (t-1)&1, then store ----
        if (t > 0) {
            const int n0 = ch * INV_CHUNK + (t - 1) * INV_TN;
            const uint32_t roff = (uint32_t)((t - 1) & 1) * I_BUF;
#pragma unroll
            for (int ni = 0; ni < 8; ++ni)
#pragma unroll
                for (int q = 0; q < 4; ++q) acc[ni][q] = 0.f;
#pragma unroll
            for (int ks = 0; ks < 8; ++ks) {
                const uint32_t co = (uint32_t)(ks * 16 * 2);
                uint32_t ah[4], bh[4][4];
                ldsm4(ah, Aa + co);
#pragma unroll
                for (int g = 0; g < 4; ++g)
                    ldsm4(bh[g], Ba + roff + g * (16 * INV_S * 2) + co);
#pragma unroll
                for (int ni = 0; ni < 8; ++ni) {
                    int g = ni >> 1, h = ni & 1;
                    mma_f16(acc[ni], ah, bh[g][h], bh[g][h + 2]);
                }
            }
#pragma unroll
            for (int ni = 0; ni < 8; ++ni) {
                int n = n0 + nh + 8 * ni + 2 * (lane & 3);
                float2 v0 = make_float2(64.f * acc[ni][0], 64.f * acc[ni][1]);
                float2 v1 = make_float2(64.f * acc[ni][2], 64.f * acc[ni][3]);
                *reinterpret_cast<float2*>(&out[((size_t)(b * NC + orow)) * NPTS + n])     = v0;
                *reinterpret_cast<float2*>(&out[((size_t)(b * NC + orow + 8)) * NPTS + n]) = v1;
            }
        }
    }
}

// ---------------------------------------------------------------------------
extern "C" void kernel_launch(void* const* d_in, const int* in_sizes, int n_in,
                              void* d_out, int out_size) {
    const float* x     = (const float*)d_in[0];
    const float* x_in  = (const float*)d_in[1];
    const float* x_out = (const float*)d_in[2];
    const float* w1    = (const float*)d_in[3];
    const float* w2    = (const float*)d_in[4];
    float* out = (float*)d_out;

    cudaFuncSetAttribute(fwd_kernel, cudaFuncAttributeMaxDynamicSharedMemorySize, F_TOT);
    cudaFuncSetAttribute(inv_kernel, cudaFuncAttributeMaxDynamicSharedMemorySize, I_TOT);

    fwd_kernel<<<dim3(NCH, NB), 256, F_TOT>>>(x, x_in);
    mix_kernel<<<dim3(32, 2, NB), 64>>>(w1, w2);
    inv_kernel<<<dim3(NCHI, NB), 256, I_TOT>>>(x_out, out);
}

// round 8
// speedup vs baseline: 1.5797x; 1.1547x over previous
#include <cuda_runtime.h>
#include <cuda_fp16.h>
#include <cstdint>

#define NB 8
#define NC 64
#define NPTS 16384
#define NJ 128
#define NCH 32
#define FWD_CHUNK 512
#define FWD_TN 64
#define FWD_TILES 8
#define NCHI 32
#define INV_CHUNK 512
#define INV_TN 128
#define INV_TILES 4
#define TWO_PI_F 6.28318530717958647692f

#define FWD_AS 72   // fwd row stride (elems), 144 B
#define INV_S 136   // inv row stride (elems), 272 B

// fwd smem per buffer: A basis [128 j][72] f16 = 18432 ; B x [64 c][72] f16 = 9216
#define F_A   0
#define F_B   18432
#define F_BUF 27648
#define F_TOT (2 * F_BUF)       // 55296
// inv smem: MY f16 static + basis double buffer
#define I_A   0
#define I_B   17408
#define I_BUF 34816
#define I_TOT (I_B + 2 * I_BUF) // 87040

__device__ float g_FTp[(size_t)NB * NCH * NJ * NC]; // 8 MB
__device__ float g_MY[(size_t)NB * NJ * NC];        // 256 KB

extern __shared__ __align__(16) char dsm[];

// ---------------------------------------------------------------------------
// helpers
// ---------------------------------------------------------------------------
__device__ __forceinline__ uint32_t smem_u32(const void* p) {
    uint32_t a;
    asm("{ .reg .u64 t; cvta.to.shared.u64 t, %1; cvt.u32.u64 %0, t; }" : "=r"(a) : "l"(p));
    return a;
}
__device__ __forceinline__ void ldsm4(uint32_t* r, uint32_t addr) {
    asm volatile("ldmatrix.sync.aligned.m8n8.x4.shared.b16 {%0,%1,%2,%3}, [%4];"
                 : "=r"(r[0]), "=r"(r[1]), "=r"(r[2]), "=r"(r[3]) : "r"(addr));
}
__device__ __forceinline__ void mma_f16(float* d, const uint32_t* a, uint32_t b0, uint32_t b1) {
    asm volatile("mma.sync.aligned.m16n8k16.row.col.f32.f16.f16.f32 "
                 "{%0,%1,%2,%3}, {%4,%5,%6,%7}, {%8,%9}, {%0,%1,%2,%3};"
                 : "+f"(d[0]), "+f"(d[1]), "+f"(d[2]), "+f"(d[3])
                 : "r"(a[0]), "r"(a[1]), "r"(a[2]), "r"(a[3]), "r"(b0), "r"(b1));
}
__device__ __forceinline__ uint32_t pk2h(__half a, __half b) {
    return (uint32_t)__half_as_ushort(a) | ((uint32_t)__half_as_ushort(b) << 16);
}

// ---------------------------------------------------------------------------
// Forward: g_FTp[b][ch][j=128][c=64] = sum_n Bas[j][n] * x[c][n] (512-chunk)
// Single-pass f16. TN=64 tiles, double-buffered, 16-step chains, 3 CTAs/SM.
// ---------------------------------------------------------------------------
__global__ __launch_bounds__(256, 3) void fwd_kernel(const float* __restrict__ x,
                                                     const float* __restrict__ x_in) {
    const int b = blockIdx.y, ch = blockIdx.x;
    const int tid = threadIdx.x, wid = tid >> 5, lane = tid & 31;

    const int j0 = (wid >> 2) * 64;
    const int c0 = (wid & 3) * 16;

    const uint32_t base = smem_u32(dsm);
    const uint32_t a_row = (uint32_t)(j0 + (lane & 7) + ((lane >> 3) & 1) * 8);
    const uint32_t a_col = (uint32_t)((lane >> 4) * 8);
    const uint32_t b_row = (uint32_t)(c0 + (lane & 7) + ((lane >> 3) & 1) * 8);
    const uint32_t Aa = base + F_A + (a_row * FWD_AS + a_col) * 2;
    const uint32_t Ba = base + F_B + (b_row * FWD_AS + a_col) * 2;

    // staging params: x tile [64 c][64 n]; thread stages 16 n of one c row
    const int cc = tid >> 2;
    const int nq = (tid & 3) * 16;
    const float* xr = x + ((size_t)b * NC + cc) * NPTS;

    // basis chain: 1 chain/thread (n 0-63, br 0-1, khalf 0-1), 16 steps
    const int cn  = tid & 63;
    const int cbr = (tid >> 6) & 1;
    const int ckh = tid >> 7;
    const int jc = cbr * 64 + ckh * 16;
    const int js = jc + 32;

    float acc[4][2][4];
#pragma unroll
    for (int mi = 0; mi < 4; ++mi)
#pragma unroll
        for (int ni = 0; ni < 2; ++ni)
#pragma unroll
            for (int q = 0; q < 4; ++q) acc[mi][ni][q] = 0.f;

    for (int t = 0; t < FWD_TILES; ++t) {
        const int n0 = ch * FWD_CHUNK + t * FWD_TN;
        const uint32_t woff = (uint32_t)(t & 1) * F_BUF;
        __half* AS = (__half*)(dsm + woff + F_A);
        __half* BS = (__half*)(dsm + woff + F_B);

        __syncthreads();

        // ---- issue long-latency loads for tile t ----
        float4 xv[4];
#pragma unroll
        for (int g = 0; g < 4; ++g)
            xv[g] = *reinterpret_cast<const float4*>(xr + n0 + nq + 4 * g);
        float p = x_in[((size_t)b * NPTS + n0 + cn) * 2 + cbr];
        float c1r, c1i, cr, ci;
        {
            float f = p - rintf(p);
            __sincosf(TWO_PI_F * f, &c1i, &c1r);
        }
        if (ckh == 0) { cr = 1.f; ci = 0.f; }
        else {
            float f = 16.f * p;
            f -= rintf(f);
            __sincosf(TWO_PI_F * f, &ci, &cr);
        }

        // ---- MMA tile t-1 (other buffer) overlapped with staging ----
        if (t > 0) {
            const uint32_t roff = (uint32_t)((t - 1) & 1) * F_BUF;
#pragma unroll
            for (int ks = 0; ks < 4; ++ks) {
                const uint32_t co = roff + (uint32_t)(ks * 16 * 2);
                uint32_t ah[4][4], bh[4];
#pragma unroll
                for (int mi = 0; mi < 4; ++mi)
                    ldsm4(ah[mi], Aa + mi * (16 * FWD_AS * 2) + co);
                ldsm4(bh, Ba + co);
#pragma unroll
                for (int mi = 0; mi < 4; ++mi)
#pragma unroll
                    for (int ni = 0; ni < 2; ++ni)
                        mma_f16(acc[mi][ni], ah[mi], bh[ni], bh[ni + 2]);
            }
        }

        // ---- store x tile f16 ----
#pragma unroll
        for (int g = 0; g < 4; ++g) {
            int col = nq + 4 * g;
            *reinterpret_cast<uint32_t*>(&BS[cc * FWD_AS + col]) =
                pk2h(__float2half_rn(xv[g].x), __float2half_rn(xv[g].y));
            *reinterpret_cast<uint32_t*>(&BS[cc * FWD_AS + col + 2]) =
                pk2h(__float2half_rn(xv[g].z), __float2half_rn(xv[g].w));
        }
        // ---- basis chain (16 steps, single f16) ----
#pragma unroll
        for (int k = 0; k < 16; ++k) {
            AS[(jc + k) * FWD_AS + cn] = __float2half_rn(cr);
            AS[(js + k) * FWD_AS + cn] = __float2half_rn(ci);
            float nr = fmaf(cr, c1r, -ci * c1i);
            float ni_ = fmaf(cr, c1i, ci * c1r);
            cr = nr; ci = ni_;
        }
    }
    // drain last tile
    __syncthreads();
    {
        const uint32_t roff = (uint32_t)((FWD_TILES - 1) & 1) * F_BUF;
#pragma unroll
        for (int ks = 0; ks < 4; ++ks) {
            const uint32_t co = roff + (uint32_t)(ks * 16 * 2);
            uint32_t ah[4][4], bh[4];
#pragma unroll
            for (int mi = 0; mi < 4; ++mi)
                ldsm4(ah[mi], Aa + mi * (16 * FWD_AS * 2) + co);
            ldsm4(bh, Ba + co);
#pragma unroll
            for (int mi = 0; mi < 4; ++mi)
#pragma unroll
                for (int ni = 0; ni < 2; ++ni)
                    mma_f16(acc[mi][ni], ah[mi], bh[ni], bh[ni + 2]);
        }
    }

    // epilogue: D[j][c] -> g_FTp
    float* outp = g_FTp + ((size_t)(b * NCH + ch)) * NJ * NC;
#pragma unroll
    for (int mi = 0; mi < 4; ++mi)
#pragma unroll
        for (int ni = 0; ni < 2; ++ni) {
            int jrow = j0 + 16 * mi + (lane >> 2);
            int ccol = c0 + 8 * ni + 2 * (lane & 3);
            float2 v0 = make_float2(acc[mi][ni][0], acc[mi][ni][1]);
            float2 v1 = make_float2(acc[mi][ni][2], acc[mi][ni][3]);
            *reinterpret_cast<float2*>(&outp[jrow * NC + ccol])       = v0;
            *reinterpret_cast<float2*>(&outp[(jrow + 8) * NC + ccol]) = v1;
        }
}

// ---------------------------------------------------------------------------
// Mix: reduce chunk partials, apply complex weights (no x64 fold here).
//  g_MY[b][br*64+k][o] = mr ; g_MY[b][br*64+32+k][o] = -mi
// ---------------------------------------------------------------------------
__global__ __launch_bounds__(64) void mix_kernel(const float* __restrict__ w1,
                                                 const float* __restrict__ w2) {
    const int k  = blockIdx.x;
    const int br = blockIdx.y;
    const int b  = blockIdx.z;
    const int o  = threadIdx.x;

    __shared__ float Ac[NC], As[NC];

    for (int v = threadIdx.x; v < 2 * NC; v += 64) {
        int cs = v >> 6;
        int i  = v & 63;
        int j  = br * 64 + cs * 32 + k;
        float s = 0.f;
        const float* basep = g_FTp + (size_t)b * NCH * NJ * NC + (size_t)j * NC + i;
        for (int c2 = 0; c2 < NCH; ++c2) s += basep[(size_t)c2 * NJ * NC];
        if (cs == 0) Ac[i] = s; else As[i] = s;
    }
    __syncthreads();

    const float* W = (br == 0) ? w1 : w2;
    float mr = 0.f, mi = 0.f;
    for (int i = 0; i < NC; ++i) {
        float2 w = *reinterpret_cast<const float2*>(W + (((size_t)i * 64 + o) * 32 + k) * 2);
        float ac = Ac[i], as = As[i];
        mr = fmaf(ac, w.x, mr);
        mr = fmaf(as, w.y, mr);
        mi = fmaf(ac, w.y, mi);
        mi = fmaf(-as, w.x, mi);
    }
    g_MY[((size_t)b * NJ + br * 64 + k) * NC + o]      = mr;
    g_MY[((size_t)b * NJ + br * 64 + 32 + k) * NC + o] = -mi;
}

// ---------------------------------------------------------------------------
// Inverse: out[b][o][n] = 64 * sum_j MY[j][o] * Bas_out[j][n]
// A = MY single f16 (static), B = basis single f16 (double-buffered).
// ---------------------------------------------------------------------------
__global__ __launch_bounds__(256, 2) void inv_kernel(const float* __restrict__ x_out,
                                                     float* __restrict__ out) {
    const int b = blockIdx.y, ch = blockIdx.x;
    const int tid = threadIdx.x, wid = tid >> 5, lane = tid & 31;

    __half* AS = (__half*)(dsm + I_A);

    // stage MY once: [o rows][j cols], single f16
    for (int v = tid; v < NJ * NC; v += 256) {
        int o = v & 63;
        int j = v >> 6;
        AS[o * INV_S + j] = __float2half_rn(g_MY[((size_t)b * NJ + j) * NC + o]);
    }

    const int o0 = (wid & 3) * 16;
    const int nh = (wid >> 2) * 64;

    const uint32_t base = smem_u32(dsm);
    const uint32_t a_row = (uint32_t)(o0 + (lane & 7) + ((lane >> 3) & 1) * 8);
    const uint32_t kcol = (uint32_t)((lane >> 4) * 8);
    const uint32_t Aa = base + I_A + (a_row * INV_S + kcol) * 2;
    const uint32_t b_row = (uint32_t)(nh + (lane & 7) + ((lane >> 3) & 1) * 8);
    const uint32_t Ba = base + I_B + (b_row * INV_S + kcol) * 2;

    float acc[8][4];
    const int orow = o0 + (lane >> 2);

    for (int t = 0; t < INV_TILES + 1; ++t) {
        __syncthreads();
        // ---- stage basis tile t into buf t&1 ----
        if (t < INV_TILES) {
            const int n0 = ch * INV_CHUNK + t * INV_TN;
            char* Bbuf = dsm + I_B + (uint32_t)(t & 1) * I_BUF;
#pragma unroll
            for (int r = 0; r < 2; ++r) {
                int id  = tid + r * 256;
                int n   = id & 127;
                int cbr = (id >> 7) & 1;
                int ckh = id >> 8;
                float p = x_out[((size_t)b * NPTS + n0 + n) * 2 + cbr];
                float c1r, c1i, cr, ci;
                {
                    float f = p - rintf(p);
                    __sincosf(TWO_PI_F * f, &c1i, &c1r);
                }
                if (ckh == 0) { cr = 1.f; ci = 0.f; }
                else {
                    float f = 16.f * p;
                    f -= rintf(f);
                    __sincosf(TWO_PI_F * f, &ci, &cr);
                }
                uint32_t chb[8], shb[8];
#pragma unroll
                for (int kp = 0; kp < 8; ++kp) {
                    __half hc0 = __float2half_rn(cr);
                    __half hs0 = __float2half_rn(ci);
                    {
                        float nr = fmaf(cr, c1r, -ci * c1i);
                        float ni_ = fmaf(cr, c1i, ci * c1r);
                        cr = nr; ci = ni_;
                    }
                    __half hc1 = __float2half_rn(cr);
                    __half hs1 = __float2half_rn(ci);
                    {
                        float nr = fmaf(cr, c1r, -ci * c1i);
                        float ni_ = fmaf(cr, c1i, ci * c1r);
                        cr = nr; ci = ni_;
                    }
                    chb[kp] = pk2h(hc0, hc1);
                    shb[kp] = pk2h(hs0, hs1);
                }
                uint32_t rowb = (uint32_t)(n * (INV_S * 2) + cbr * 128 + ckh * 32);
                char* Bp = Bbuf + rowb;
                *reinterpret_cast<uint4*>(Bp)           = *reinterpret_cast<uint4*>(&chb[0]);
                *reinterpret_cast<uint4*>(Bp + 16)      = *reinterpret_cast<uint4*>(&chb[4]);
                *reinterpret_cast<uint4*>(Bp + 64)      = *reinterpret_cast<uint4*>(&shb[0]);
                *reinterpret_cast<uint4*>(Bp + 64 + 16) = *reinterpret_cast<uint4*>(&shb[4]);
            }
        }
        // ---- MMA tile t-1 from buf (t-1)&1, then store ----
        if (t > 0) {
            const int n0 = ch * INV_CHUNK + (t - 1) * INV_TN;
            const uint32_t roff = (uint32_t)((t - 1) & 1) * I_BUF;
#pragma unroll
            for (int ni = 0; ni < 8; ++ni)
#pragma unroll
                for (int q = 0; q < 4; ++q) acc[ni][q] = 0.f;
#pragma unroll
            for (int ks = 0; ks < 8; ++ks) {
                const uint32_t co = (uint32_t)(ks * 16 * 2);
                uint32_t ah[4], bh[4][4];
                ldsm4(ah, Aa + co);
#pragma unroll
                for (int g = 0; g < 4; ++g)
                    ldsm4(bh[g], Ba + roff + g * (16 * INV_S * 2) + co);
#pragma unroll
                for (int ni = 0; ni < 8; ++ni) {
                    int g = ni >> 1, h = ni & 1;
                    mma_f16(acc[ni], ah, bh[g][h], bh[g][h + 2]);
                }
            }
#pragma unroll
            for (int ni = 0; ni < 8; ++ni) {
                int n = n0 + nh + 8 * ni + 2 * (lane & 3);
                float2 v0 = make_float2(64.f * acc[ni][0], 64.f * acc[ni][1]);
                float2 v1 = make_float2(64.f * acc[ni][2], 64.f * acc[ni][3]);
                *reinterpret_cast<float2*>(&out[((size_t)(b * NC + orow)) * NPTS + n])     = v0;
                *reinterpret_cast<float2*>(&out[((size_t)(b * NC + orow + 8)) * NPTS + n]) = v1;
            }
        }
    }
}

// ---------------------------------------------------------------------------
extern "C" void kernel_launch(void* const* d_in, const int* in_sizes, int n_in,
                              void* d_out, int out_size) {
    const float* x     = (const float*)d_in[0];
    const float* x_in  = (const float*)d_in[1];
    const float* x_out = (const float*)d_in[2];
    const float* w1    = (const float*)d_in[3];
    const float* w2    = (const float*)d_in[4];
    float* out = (float*)d_out;

    cudaFuncSetAttribute(fwd_kernel, cudaFuncAttributeMaxDynamicSharedMemorySize, F_TOT);
    cudaFuncSetAttribute(inv_kernel, cudaFuncAttributeMaxDynamicSharedMemorySize, I_TOT);

    fwd_kernel<<<dim3(NCH, NB), 256, F_TOT>>>(x, x_in);
    mix_kernel<<<dim3(32, 2, NB), 64>>>(w1, w2);
    inv_kernel<<<dim3(NCHI, NB), 256, I_TOT>>>(x_out, out);
}